// round 5
// baseline (speedup 1.0000x reference)
#include <cuda_runtime.h>

#define LVLS 16
#define TSIZE 16384
#define NPTS 262144
#define TMASK 16383
#define PRIME1 (-1640531535)   // 2654435761 wrapped to int32
#define PRIME2 (805459861)
#define CTAS_PER_LVL 9
#define NTHREADS 1024

// One CTA per (level, point-chunk). The level's 128KB table lives in shared
// memory; each thread handles points with 8 random LDS.64 gathers per point.
__global__ __launch_bounds__(NTHREADS, 1)
void hash_enc_kernel(const float* __restrict__ x,
                     const float* __restrict__ emb,
                     float* __restrict__ out)
{
    extern __shared__ float2 table[];   // TSIZE float2 = 128KB
    const int level = blockIdx.y;

    // Cooperative table load (float4-vectorized, coalesced)
    {
        const float4* src = (const float4*)(emb + (size_t)level * TSIZE * 2);
        float4* dst = (float4*)table;
        #pragma unroll
        for (int i = threadIdx.x; i < (TSIZE * 2) / 4; i += NTHREADS)
            dst[i] = src[i];
    }
    __syncthreads();

    // Per-level resolution: N_l = Nmin * b^l, b = exp((ln Nmax - ln Nmin)/L)
    const float bgrow = expf((logf(512.0f) - logf(16.0f)) * (1.0f / 16.0f));
    const float scale = 16.0f * powf(bgrow, (float)level);

    const int stride = CTAS_PER_LVL * NTHREADS;
    for (int n = blockIdx.x * NTHREADS + threadIdx.x; n < NPTS; n += stride) {
        const float x0 = x[n * 3 + 0];
        const float x1 = x[n * 3 + 1];
        const float x2 = x[n * 3 + 2];

        const float u0 = x0 * scale, u1 = x1 * scale, u2 = x2 * scale;
        const float f0 = floorf(u0), f1 = floorf(u1), f2 = floorf(u2);
        const int   i0 = (int)f0,    i1 = (int)f1,    i2 = (int)f2;
        // d = ceil-floor is 1 when frac>0, else 0 -> diff == frac in both cases.
        const float d0 = u0 - f0, d1 = u1 - f1, d2 = u2 - f2;
        const float o0 = 1.0f - d0, o1 = 1.0f - d1, o2 = 1.0f - d2;

        // Pre-multiplied corner hash terms (wrapping int32, matches torch/jnp)
        const int pl0 = i0;                  const int ph0 = pl0 + 1;      // prime 1
        const int pl1 = i1 * PRIME1;         const int ph1 = pl1 + PRIME1;
        const int pl2 = i2 * PRIME2;         const int ph2 = pl2 + PRIME2;
        // When frac==0 the reference uses hi==lo, but those corners carry an
        // exactly-zero weight here (d_i == 0.0f), so hi = lo+1 is safe.

        float ax = 0.0f, ay = 0.0f;
        #pragma unroll
        for (int k = 0; k < 8; ++k) {
            const int a = (k >> 2) & 1;     // dim0
            const int b = (k >> 1) & 1;     // dim1
            const int c = k & 1;            // dim2
            const int h = (a ? ph0 : pl0) ^ (b ? ph1 : pl1) ^ (c ? ph2 : pl2);
            const int idx = h & TMASK;      // == jnp.mod(h, 16384) for int32
            const float w = (a ? d0 : o0) * (b ? d1 : o1) * (c ? d2 : o2);
            const float2 v = table[idx];
            ax = fmaf(w, v.x, ax);
            ay = fmaf(w, v.y, ay);
        }

        // out layout: (N, L*F) row-major
        float2* op = (float2*)(out + (size_t)n * (LVLS * 2) + level * 2);
        *op = make_float2(ax, ay);
    }
}

extern "C" void kernel_launch(void* const* d_in, const int* in_sizes, int n_in,
                              void* d_out, int out_size)
{
    // metadata order: x (N*3 = 786432 floats), embeddings (L*T*F = 524288 floats).
    // Detect by size to be robust.
    const float* x;
    const float* emb;
    if (in_sizes[0] == NPTS * 3) {
        x = (const float*)d_in[0];
        emb = (const float*)d_in[1];
    } else {
        x = (const float*)d_in[1];
        emb = (const float*)d_in[0];
    }
    float* out = (float*)d_out;

    // 128KB dynamic smem needs opt-in (idempotent; capturable — host-side attr)
    cudaFuncSetAttribute(hash_enc_kernel,
                         cudaFuncAttributeMaxDynamicSharedMemorySize,
                         TSIZE * 2 * (int)sizeof(float));

    dim3 grid(CTAS_PER_LVL, LVLS);   // 144 CTAs = one full wave @ 1 CTA/SM
    hash_enc_kernel<<<grid, NTHREADS, TSIZE * 2 * sizeof(float)>>>(x, emb, out);
}

// round 6
// speedup vs baseline: 1.2446x; 1.2446x over previous
#include <cuda_runtime.h>

#define LVLS 16
#define TSIZE 16384
#define NPTS 262144
#define TMASK 16383
#define PRIME1 (-1640531535)   // 2654435761 wrapped to int32
#define PRIME2 (805459861)
#define CTAS_PER_LVL 9
#define NTHREADS 1024
#define TPTS 256               // points per transpose tile

// Scratch in (L, N) layout of float2 — 33.5MB static device array (allowed).
__device__ float2 g_scr[(size_t)LVLS * NPTS];

// ---------------------------------------------------------------------------
// Kernel 1: hash-grid gather. One CTA per (level, point-chunk); the level's
// 128KB table lives in shared memory. Stores go to scratch in (L,N,2) layout
// so each warp-store is 256B contiguous (2 L1 wavefronts, not 32).
// ---------------------------------------------------------------------------
__global__ __launch_bounds__(NTHREADS, 1)
void hash_enc_kernel(const float* __restrict__ x,
                     const float* __restrict__ emb)
{
    extern __shared__ float2 table[];   // TSIZE float2 = 128KB
    const int level = blockIdx.y;

    // Cooperative table load (float4-vectorized, coalesced)
    {
        const float4* src = (const float4*)(emb + (size_t)level * TSIZE * 2);
        float4* dst = (float4*)table;
        #pragma unroll
        for (int i = threadIdx.x; i < (TSIZE * 2) / 4; i += NTHREADS)
            dst[i] = src[i];
    }
    __syncthreads();

    // Per-level resolution: N_l = Nmin * b^l  (identical formula to the
    // passing kernel — do not perturb index-determining arithmetic)
    const float bgrow = expf((logf(512.0f) - logf(16.0f)) * (1.0f / 16.0f));
    const float scale = 16.0f * powf(bgrow, (float)level);

    float2* scr = g_scr + (size_t)level * NPTS;

    const int stride = CTAS_PER_LVL * NTHREADS;
    for (int n = blockIdx.x * NTHREADS + threadIdx.x; n < NPTS; n += stride) {
        const float x0 = x[n * 3 + 0];
        const float x1 = x[n * 3 + 1];
        const float x2 = x[n * 3 + 2];

        const float u0 = x0 * scale, u1 = x1 * scale, u2 = x2 * scale;
        const float f0 = floorf(u0), f1 = floorf(u1), f2 = floorf(u2);
        const int   i0 = (int)f0,    i1 = (int)f1,    i2 = (int)f2;
        // d = ceil-floor is 1 when frac>0, else 0 -> diff == frac either way.
        const float d0 = u0 - f0, d1 = u1 - f1, d2 = u2 - f2;
        const float o0 = 1.0f - d0, o1 = 1.0f - d1, o2 = 1.0f - d2;

        // Pre-multiplied corner hash terms (wrapping int32, matches jnp/torch)
        const int pl0 = i0;                  const int ph0 = pl0 + 1;
        const int pl1 = i1 * PRIME1;         const int ph1 = pl1 + PRIME1;
        const int pl2 = i2 * PRIME2;         const int ph2 = pl2 + PRIME2;
        // frac==0 corners carry an exactly-zero weight, so hi = lo+1 is safe.

        float ax = 0.0f, ay = 0.0f;
        #pragma unroll
        for (int k = 0; k < 8; ++k) {
            const int a = (k >> 2) & 1;     // dim0
            const int b = (k >> 1) & 1;     // dim1
            const int c = k & 1;            // dim2
            const int h = (a ? ph0 : pl0) ^ (b ? ph1 : pl1) ^ (c ? ph2 : pl2);
            const int idx = h & TMASK;      // == mod 16384 for int32
            const float w = (a ? d0 : o0) * (b ? d1 : o1) * (c ? d2 : o2);
            const float2 v = table[idx];
            ax = fmaf(w, v.x, ax);
            ay = fmaf(w, v.y, ay);
        }

        // (L, N, 2) scratch layout: fully coalesced warp store (256B)
        scr[n] = make_float2(ax, ay);
    }
}

// ---------------------------------------------------------------------------
// Kernel 2: (L, N, 2) -> (N, L*2) transpose via smem tiles. Input is
// L2-resident (just written, 33.5MB << 126MB L2). Both gmem sides coalesced;
// final stores are 512B-contiguous per warp (4 full 128B rows).
// ---------------------------------------------------------------------------
__global__ __launch_bounds__(TPTS)
void transpose_kernel(float* __restrict__ out)
{
    __shared__ float2 tile[TPTS][LVLS + 1];   // +1 pad: ~34.8KB

    const int n0 = blockIdx.x * TPTS;
    const int t  = threadIdx.x;

    // Load: for each level, 256 consecutive float2 (coalesced);
    // smem store banks = (34t + 2l) % 32 -> distinct across lanes.
    #pragma unroll
    for (int l = 0; l < LVLS; ++l)
        tile[t][l] = g_scr[(size_t)l * NPTS + n0 + t];
    __syncthreads();

    // Store: warp writes 4 consecutive 128B output rows per pass.
    const int q  = t & 7;    // which float4 (pair of levels) within the row
    const int pl = t >> 3;   // point-within-tile offset
    float4* out4 = (float4*)out;
    #pragma unroll
    for (int i = 0; i < TPTS / 32; ++i) {
        const int p = i * 32 + pl;
        const float2 a = tile[p][2 * q];
        const float2 b = tile[p][2 * q + 1];
        out4[(size_t)(n0 + p) * (LVLS / 2) + q] = make_float4(a.x, a.y, b.x, b.y);
    }
}

extern "C" void kernel_launch(void* const* d_in, const int* in_sizes, int n_in,
                              void* d_out, int out_size)
{
    const float* x;
    const float* emb;
    if (in_sizes[0] == NPTS * 3) {
        x = (const float*)d_in[0];
        emb = (const float*)d_in[1];
    } else {
        x = (const float*)d_in[1];
        emb = (const float*)d_in[0];
    }
    float* out = (float*)d_out;

    cudaFuncSetAttribute(hash_enc_kernel,
                         cudaFuncAttributeMaxDynamicSharedMemorySize,
                         TSIZE * 2 * (int)sizeof(float));

    dim3 grid(CTAS_PER_LVL, LVLS);   // 144 CTAs = one full wave @ 1 CTA/SM
    hash_enc_kernel<<<grid, NTHREADS, TSIZE * 2 * sizeof(float)>>>(x, emb);

    transpose_kernel<<<NPTS / TPTS, TPTS>>>(out);
}

// round 7
// speedup vs baseline: 1.2523x; 1.0062x over previous
#include <cuda_runtime.h>

#define LVLS 16
#define TSIZE 16384
#define NPTS 262144
#define TMASK 16383
#define PRIME1 (-1640531535)   // 2654435761 wrapped to int32
#define PRIME2 (805459861)
#define CTAS_PER_LVL 9
#define NTHREADS 1024
#define TPTS 512               // points per transpose tile
#define TTHREADS 256           // transpose block size (2 points/thread)
#define TPITCH (TPTS + 2)      // float2 pitch: 514 -> 4112B rows, 16B aligned

// Scratch in (L, N) layout of float2 — 33.5MB static device array (allowed).
__device__ float2 g_scr[(size_t)LVLS * NPTS];

// ---------------------------------------------------------------------------
// Kernel 1: hash-grid gather. One CTA per (level, point-chunk); the level's
// 128KB table lives in shared memory. Stores go to scratch in (L,N,2) layout
// so each warp-store is 256B contiguous.
// ---------------------------------------------------------------------------
__global__ __launch_bounds__(NTHREADS, 1)
void hash_enc_kernel(const float* __restrict__ x,
                     const float* __restrict__ emb)
{
    extern __shared__ float2 table[];   // TSIZE float2 = 128KB
    const int level = blockIdx.y;

    // Cooperative table load (float4-vectorized, coalesced)
    {
        const float4* src = (const float4*)(emb + (size_t)level * TSIZE * 2);
        float4* dst = (float4*)table;
        #pragma unroll
        for (int i = threadIdx.x; i < (TSIZE * 2) / 4; i += NTHREADS)
            dst[i] = src[i];
    }
    __syncthreads();

    // Per-level resolution: N_l = Nmin * b^l  (identical formula to the
    // passing kernel — do not perturb index-determining arithmetic)
    const float bgrow = expf((logf(512.0f) - logf(16.0f)) * (1.0f / 16.0f));
    const float scale = 16.0f * powf(bgrow, (float)level);

    float2* scr = g_scr + (size_t)level * NPTS;

    const int stride = CTAS_PER_LVL * NTHREADS;
    for (int n = blockIdx.x * NTHREADS + threadIdx.x; n < NPTS; n += stride) {
        const float x0 = x[n * 3 + 0];
        const float x1 = x[n * 3 + 1];
        const float x2 = x[n * 3 + 2];

        const float u0 = x0 * scale, u1 = x1 * scale, u2 = x2 * scale;
        const float f0 = floorf(u0), f1 = floorf(u1), f2 = floorf(u2);
        const int   i0 = (int)f0,    i1 = (int)f1,    i2 = (int)f2;
        // d = ceil-floor is 1 when frac>0, else 0 -> diff == frac either way.
        const float d0 = u0 - f0, d1 = u1 - f1, d2 = u2 - f2;
        const float o0 = 1.0f - d0, o1 = 1.0f - d1, o2 = 1.0f - d2;

        // Pre-multiplied corner hash terms (wrapping int32, matches jnp/torch)
        const int pl0 = i0;                  const int ph0 = pl0 + 1;
        const int pl1 = i1 * PRIME1;         const int ph1 = pl1 + PRIME1;
        const int pl2 = i2 * PRIME2;         const int ph2 = pl2 + PRIME2;
        // frac==0 corners carry an exactly-zero weight, so hi = lo+1 is safe.

        float ax = 0.0f, ay = 0.0f;
        #pragma unroll
        for (int k = 0; k < 8; ++k) {
            const int a = (k >> 2) & 1;     // dim0
            const int b = (k >> 1) & 1;     // dim1
            const int c = k & 1;            // dim2
            const int h = (a ? ph0 : pl0) ^ (b ? ph1 : pl1) ^ (c ? ph2 : pl2);
            const int idx = h & TMASK;      // == mod 16384 for int32
            const float w = (a ? d0 : o0) * (b ? d1 : o1) * (c ? d2 : o2);
            const float2 v = table[idx];
            ax = fmaf(w, v.x, ax);
            ay = fmaf(w, v.y, ay);
        }

        // (L, N, 2) scratch layout: fully coalesced warp store (256B)
        scr[n] = make_float2(ax, ay);
    }
}

// ---------------------------------------------------------------------------
// Kernel 2: (L, N, 2) -> (N, L*2) transpose. 512-point tiles, 2 points per
// thread via float4 loads (16 LDG.128/thread, high MLP), level-major smem so
// incoming float4 is one conflict-free STS.128. Store: warp writes 4 full
// consecutive 128B output rows per STG.128 pass (512B contiguous).
// ---------------------------------------------------------------------------
__global__ __launch_bounds__(TTHREADS)
void transpose_kernel(float* __restrict__ out)
{
    __shared__ float2 tile[LVLS][TPITCH];   // 16 x 514 x 8B = 65.8KB

    const int n0 = blockIdx.x * TPTS;
    const int t  = threadIdx.x;

    // Load: thread t fetches points (n0+2t, n0+2t+1) for all 16 levels.
    const float4* scr4 = (const float4*)g_scr;
    #pragma unroll
    for (int l = 0; l < LVLS; ++l) {
        const float4 v = scr4[(size_t)l * (NPTS / 2) + (n0 >> 1) + t];
        *(float4*)&tile[l][2 * t] = v;      // contiguous STS.128, conflict-free
    }
    __syncthreads();

    // Store: q = float4-slot within row (pair of levels), rows p advance 32/iter.
    const int q  = t & 7;
    const int pr = t >> 3;                  // 0..31
    float4* out4 = (float4*)out;
    #pragma unroll
    for (int i = 0; i < TPTS / 32; ++i) {
        const int p = i * 32 + pr;
        const float2 a = tile[2 * q][p];
        const float2 b = tile[2 * q + 1][p];
        out4[(size_t)(n0 + p) * (LVLS / 2) + q] = make_float4(a.x, a.y, b.x, b.y);
    }
}

extern "C" void kernel_launch(void* const* d_in, const int* in_sizes, int n_in,
                              void* d_out, int out_size)
{
    const float* x;
    const float* emb;
    if (in_sizes[0] == NPTS * 3) {
        x = (const float*)d_in[0];
        emb = (const float*)d_in[1];
    } else {
        x = (const float*)d_in[1];
        emb = (const float*)d_in[0];
    }
    float* out = (float*)d_out;

    cudaFuncSetAttribute(hash_enc_kernel,
                         cudaFuncAttributeMaxDynamicSharedMemorySize,
                         TSIZE * 2 * (int)sizeof(float));

    dim3 grid(CTAS_PER_LVL, LVLS);   // 144 CTAs = one full wave @ 1 CTA/SM
    hash_enc_kernel<<<grid, NTHREADS, TSIZE * 2 * sizeof(float)>>>(x, emb);

    transpose_kernel<<<NPTS / TPTS, TTHREADS>>>(out);
}